// round 17
// baseline (speedup 1.0000x reference)
#include <cuda_runtime.h>
#include <cstdint>

#define HH 2048
#define WW 2048
#define NB 148
#define NT 1024
#define NW 32
#define CBLK 74
#define TOT4 (HH*WW/4)          // 1,048,576 float4 per channel
#define STR (CBLK*NT)           // 75,776
#define TMAX 16                 // per-thread tile maxima kept in regs (rows <= 32)

// Only cross-kernel state: phase-0 block partials, fully rewritten each launch.
__device__ float4 g_p0[NB];

__device__ __forceinline__ float neg_inf() { return __int_as_float(0xff800000); }
__device__ __forceinline__ float fmax4(float4 A) {
    return fmaxf(fmaxf(A.x, A.y), fmaxf(A.z, A.w));
}

// Block-wide max, broadcast to ALL threads.
__device__ float block_max_bcast(float m) {
    __shared__ float sm[NW];
    __shared__ float sM;
    int tid = threadIdx.x;
    __syncthreads();
    #pragma unroll
    for (int o = 16; o; o >>= 1) m = fmaxf(m, __shfl_xor_sync(0xffffffffu, m, o));
    if ((tid & 31) == 0) sm[tid >> 5] = m;
    __syncthreads();
    if (tid < 32) {
        float t = sm[tid];
        #pragma unroll
        for (int o = 16; o; o >>= 1) t = fmaxf(t, __shfl_xor_sync(0xffffffffu, t, o));
        if (tid == 0) sM = t;
    }
    __syncthreads();
    return sM;
}

// Block-wide 3-way sum; result valid on threads 0..31.
__device__ void block_sum3(float &S, float &Sx, float &Sy) {
    __shared__ float ss[NW][3];
    int tid = threadIdx.x;
    __syncthreads();
    #pragma unroll
    for (int o = 16; o; o >>= 1) {
        S  += __shfl_xor_sync(0xffffffffu, S, o);
        Sx += __shfl_xor_sync(0xffffffffu, Sx, o);
        Sy += __shfl_xor_sync(0xffffffffu, Sy, o);
    }
    if ((tid & 31) == 0) { ss[tid >> 5][0] = S; ss[tid >> 5][1] = Sx; ss[tid >> 5][2] = Sy; }
    __syncthreads();
    if (tid < 32) {
        S = ss[tid][0]; Sx = ss[tid][1]; Sy = ss[tid][2];
        #pragma unroll
        for (int o = 16; o; o >>= 1) {
            S  += __shfl_xor_sync(0xffffffffu, S, o);
            Sx += __shfl_xor_sync(0xffffffffu, Sx, o);
            Sy += __shfl_xor_sync(0xffffffffu, Sy, o);
        }
    }
}

// Fixed-max accumulate (phase0 reload). Ms is the SCALED (x100) block max.
__device__ __forceinline__ void accf(float Ms, float &S, float &Sx, float &Sy,
                                     float raw, float x, float y) {
    float v = raw * 100.f;
    if (v > Ms - 88.f) {
        float e = expf(v - Ms);
        S += e; Sx += x * e; Sy += y * e;
    }
}

// ================= Kernel A: phase-0 streaming (148 blocks, no sync) =================
__global__ void __launch_bounds__(NT, 1)
phase0_kernel(const float * __restrict__ hm) {
    const int b = blockIdx.x;
    const int tid = threadIdx.x;
    const int c  = (b < CBLK) ? 0 : 1;
    const int bb = (b < CBLK) ? b : b - CBLK;
    const float4 *p4 = reinterpret_cast<const float4*>(hm + (size_t)(9 + c) * HH * WW);
    const int ibase = bb * NT + tid;

    // pass A: branch-free RAW max, 8/6 loads batched for MLP; two 7-tile groups
    float bmx[2];
    {
        float4 T0 = p4[ibase + 0 * STR];
        float4 T1 = p4[ibase + 1 * STR];
        float4 T2 = p4[ibase + 2 * STR];
        float4 T3 = p4[ibase + 3 * STR];
        float4 T4 = p4[ibase + 4 * STR];
        float4 T5 = p4[ibase + 5 * STR];
        float4 T6 = p4[ibase + 6 * STR];
        float4 T7 = p4[ibase + 7 * STR];
        float m0 = fmaxf(fmaxf(fmax4(T0), fmax4(T1)), fmaxf(fmax4(T2), fmax4(T3)));
        float m1 = fmaxf(fmax4(T4), fmaxf(fmax4(T5), fmax4(T6)));
        bmx[0] = fmaxf(m0, m1);                    // group 0 = tiles 0..6
        float4 U0 = p4[ibase + 8 * STR];
        float4 U1 = p4[ibase + 9 * STR];
        float4 U2 = p4[ibase + 10 * STR];
        float4 U3 = p4[ibase + 11 * STR];
        float4 U4 = p4[ibase + 12 * STR];
        int i13 = ibase + 13 * STR;
        float m13 = neg_inf();
        if (i13 < TOT4) { float4 U5 = p4[i13]; m13 = fmax4(U5); }
        float m2 = fmaxf(fmaxf(fmax4(U0), fmax4(U1)), fmaxf(fmax4(U2), fmax4(U3)));
        bmx[1] = fmaxf(fmaxf(fmax4(T7), m13), fmaxf(m2, fmax4(U4)));   // group 1 = tiles 7..13
    }
    float Mb = block_max_bcast(fmaxf(bmx[0], bmx[1]));

    // pass B: ballot-skip reload of qualifying 7-tile groups (L2 hits), sums rel. BLOCK max
    const float Ms     = Mb * 100.f;
    const float thrRaw = Mb - 0.88f;
    float S = 0.f, Sx = 0.f, Sy = 0.f;
    #pragma unroll
    for (int k = 0; k < 2; k++) {
        if (__any_sync(0xffffffffu, bmx[k] > thrRaw)) {
            int tlo = 7 * k, thi = 7 * k + 7;
            for (int t = tlo; t < thi; t++) {
                int idx = ibase + t * STR;
                if (idx < TOT4) {
                    float4 A = p4[idx];
                    float y  = (float)(idx >> 9);
                    float x0 = (float)((idx & 511) << 2);
                    accf(Ms, S, Sx, Sy, A.x, x0,       y);
                    accf(Ms, S, Sx, Sy, A.y, x0 + 1.f, y);
                    accf(Ms, S, Sx, Sy, A.z, x0 + 2.f, y);
                    accf(Ms, S, Sx, Sy, A.w, x0 + 3.f, y);
                }
            }
        }
    }
    block_sum3(S, Sx, Sy);
    if (tid == 0) g_p0[b] = make_float4(Mb, S, Sx, Sy);   // RAW max + relative sums
}

// ============ Kernel B: finisher + 9 band phases, ONE CTA (no inter-CTA sync) ============
__global__ void __launch_bounds__(NT, 1)
bands_kernel(const float * __restrict__ hm, float * __restrict__ out) {
    const int tid = threadIdx.x;
    const int lane = tid & 31;
    const int w = tid >> 5;
    __shared__ float s_ay, s_ay2[2];
    __shared__ float4 sP[NW];           // per-warp band partials (M scaled, S, Sx, Sy)

    // ---- Phase 0 finisher: merge 74 partials per channel ----
    for (int cc = 0; cc < 2; cc++) {
        float Mk = neg_inf(), S = 0.f, Sx = 0.f, Sy = 0.f;
        if (tid < CBLK) {
            float4 p = g_p0[cc * CBLK + tid];
            Mk = p.x; S = p.y; Sx = p.z; Sy = p.w;
        }
        float Mg = block_max_bcast(Mk);
        float e = (tid < CBLK) ? expf((Mk - Mg) * 100.f) : 0.f;
        S *= e; Sx *= e; Sy *= e;
        block_sum3(S, Sx, Sy);
        if (tid == 0) {
            float ax = Sx / S, ay = Sy / S;
            s_ay2[cc] = ay;
            out[(9 + cc) * 2 + 0] = ax; out[(9 + cc) * 2 + 1] = ay;
        }
        __syncthreads();
    }
    float yA = s_ay2[0], yB = s_ay2[1];
    float dis = __fsub_rn(yB, yA), dsum = 0.f, dnum = 0.f;

    // per-thread constants for band addressing: column fixed, row advances by 2/tile
    const int xq  = tid & 511;          // float4 column
    const int rof = tid >> 9;           // 0 or 1
    const float x0c = (float)(xq << 2);

    // ---------------- Band phases i = 8 .. 0 (2 block bars each) ----------------
    for (int i = 8; i >= 0; i--) {
        // scalar band logic, redundant in all threads; __f*_rn blocks FMA contraction
        {
            float tmp = ceilf(__fsub_rn(yB, yA));
            if (fabsf(__fsub_rn(tmp, dis)) > __fmul_rn(0.35f, dis)) {
                dsum = __fadd_rn(dsum, tmp);
                dnum = __fadd_rn(dnum, 1.0f);
                dis  = __fdiv_rn(dsum, fmaxf(dnum, 1.0f));
            }
        }
        float last_y = floorf(yA);
        float t  = __fmul_rn(1.8f, dis);
        float sr = __fsub_rn(last_y, t);
        float end_y   = rintf(__fadd_rn(sr, t));   // round-half-even = jnp.round
        float start_y = rintf(sr);
        const int r0 = (start_y <= 0.f) ? 0  : (start_y >= (float)HH       ? HH     : (int)start_y);
        const int r1 = (end_y   <  0.f) ? -1 : (end_y   >= (float)(HH - 1) ? HH - 1 : (int)end_y);
        const int rows = r1 - r0 + 1;
        const int nelt = rows * 512;                // float4 count (<=0 if empty)
        const int Tn   = (nelt + NT - 1) / NT;      // tiles per thread (= ceil(rows/2))
        const float *chan = hm + (size_t)i * HH * WW;

        float wmr = neg_inf();                      // raw warp max
        float S = 0.f, Sx = 0.f, Sy = 0.f;

        if (Tn <= TMAX) {
            // ---- fast path: fully-unrolled predicated load batches (MLP 8) ----
            const float4 *fp = reinterpret_cast<const float4*>(chan + (size_t)(r0 + rof) * WW) + xq;
            float tm[TMAX];
            {
                // batch A: tiles 0..7, 8 back-to-back predicated LDG.128
                float4 Av[8];
                #pragma unroll
                for (int tt = 0; tt < 8; tt++) {
                    Av[tt] = make_float4(neg_inf(), neg_inf(), neg_inf(), neg_inf());
                    if (r0 + rof + 2 * tt <= r1) Av[tt] = fp[tt * 1024];
                }
                #pragma unroll
                for (int tt = 0; tt < 8; tt++) { tm[tt] = fmax4(Av[tt]); wmr = fmaxf(wmr, tm[tt]); }
            }
            if (r0 + rof + 16 <= r1) {
                // batch B: tiles 8..15 (only when the band is wide enough)
                float4 Bv[8];
                #pragma unroll
                for (int tt = 0; tt < 8; tt++) {
                    Bv[tt] = make_float4(neg_inf(), neg_inf(), neg_inf(), neg_inf());
                    if (r0 + rof + 2 * (tt + 8) <= r1) Bv[tt] = fp[(tt + 8) * 1024];
                }
                #pragma unroll
                for (int tt = 0; tt < 8; tt++) { tm[tt + 8] = fmax4(Bv[tt]); wmr = fmaxf(wmr, tm[tt + 8]); }
            } else {
                #pragma unroll
                for (int tt = 8; tt < 16; tt++) tm[tt] = neg_inf();
            }
            #pragma unroll
            for (int o = 16; o; o >>= 1) wmr = fmaxf(wmr, __shfl_xor_sync(0xffffffffu, wmr, o));

            // L2 prefetch of the PREDICTED next band (window shifted up by ~dis, +-8 rows).
            // One prefetch per 128B line; pure hint, correctness-free on misprediction.
            if (i > 0 && rows > 0 && (xq & 7) == 0) {
                int d = (int)dis;
                int pr0 = r0 - d - 8; if (pr0 < 0) pr0 = 0;
                int pr1 = r1 - d + 8; if (pr1 > HH - 1) pr1 = HH - 1;
                const float *nchan = chan - (size_t)HH * WW;   // channel i-1
                int cnt = 0;
                for (int row = pr0 + rof; row <= pr1 && cnt < 32; row += 2, cnt++) {
                    const float *pp = nchan + (size_t)row * WW + (xq << 2);
                    asm volatile("prefetch.global.L2 [%0];" :: "l"(pp));
                }
            }

            const float Ms  = wmr * 100.f;
            const float thr = wmr - 0.88f;
            for (int tt = 0; tt < Tn; tt++) {
                if (__any_sync(0xffffffffu, tm[tt] > thr)) {
                    int row = r0 + rof + 2 * tt;
                    if (row <= r1) {
                        float4 A = fp[tt * 1024];
                        float e0 = expf(A.x * 100.f - Ms), e1 = expf(A.y * 100.f - Ms);
                        float e2 = expf(A.z * 100.f - Ms), e3 = expf(A.w * 100.f - Ms);
                        float es = (e0 + e1) + (e2 + e3);
                        S  += es;
                        Sx += x0c * e0 + (x0c + 1.f) * e1 + (x0c + 2.f) * e2 + (x0c + 3.f) * e3;
                        Sy += (float)row * es;
                    }
                }
            }
        } else {
            // ---- slow path (wide band): max pass + full reload with on-the-fly ballot ----
            #pragma unroll 4
            for (int tt = 0; tt < Tn; tt++) {
                int g = tt * NT + tid;
                if (g < nelt) {
                    float4 A = reinterpret_cast<const float4*>(chan + (size_t)(r0 + (g >> 9)) * WW)[g & 511];
                    wmr = fmaxf(wmr, fmax4(A));
                }
            }
            #pragma unroll
            for (int o = 16; o; o >>= 1) wmr = fmaxf(wmr, __shfl_xor_sync(0xffffffffu, wmr, o));
            const float Ms  = wmr * 100.f;
            const float thr = wmr - 0.88f;
            for (int tt = 0; tt < Tn; tt++) {
                int g = tt * NT + tid;
                bool v = g < nelt;
                float4 A;
                float mv = neg_inf();
                if (v) {
                    A = reinterpret_cast<const float4*>(chan + (size_t)(r0 + (g >> 9)) * WW)[g & 511];
                    mv = fmax4(A);
                }
                if (__any_sync(0xffffffffu, mv > thr)) {
                    if (v) {
                        float e0 = expf(A.x * 100.f - Ms), e1 = expf(A.y * 100.f - Ms);
                        float e2 = expf(A.z * 100.f - Ms), e3 = expf(A.w * 100.f - Ms);
                        float es = (e0 + e1) + (e2 + e3);
                        float x0 = (float)((g & 511) << 2);
                        S  += es;
                        Sx += x0 * e0 + (x0 + 1.f) * e1 + (x0 + 2.f) * e2 + (x0 + 3.f) * e3;
                        Sy += (float)(r0 + (g >> 9)) * es;
                    }
                }
            }
        }

        // warp partial: sums relative to warp max (no bar yet)
        #pragma unroll
        for (int o = 16; o; o >>= 1) {
            S  += __shfl_xor_sync(0xffffffffu, S, o);
            Sx += __shfl_xor_sync(0xffffffffu, Sx, o);
            Sy += __shfl_xor_sync(0xffffffffu, Sy, o);
        }
        if (lane == 0) sP[w] = make_float4(wmr * 100.f, S, Sx, Sy);   // M scaled; -inf if empty
        __syncthreads();                    // BAR A

        if (tid < 32) {
            // fold 32 warp partials (two-step logsumexp) + closed-form tail
            float4 p = sP[tid];
            float Mk = p.x, T = p.y, Tx = p.z, Ty = p.w;
            float Mg = Mk;
            #pragma unroll
            for (int o = 16; o; o >>= 1) Mg = fmaxf(Mg, __shfl_xor_sync(0xffffffffu, Mg, o));
            float e2 = (Mk == neg_inf()) ? 0.f : expf(Mk - Mg);
            T *= e2; Tx *= e2; Ty *= e2;
            #pragma unroll
            for (int o = 16; o; o >>= 1) {
                T  += __shfl_xor_sync(0xffffffffu, T, o);
                Tx += __shfl_xor_sync(0xffffffffu, Tx, o);
                Ty += __shfl_xor_sync(0xffffffffu, Ty, o);
            }
            if (tid == 0) {
                float Rn = (rows > 0) ? (float)rows : 0.f;
                float m;
                if (Rn >= 2048.f)      m = Mg;               // band covers everything
                else if (Rn > 0.f)     m = fmaxf(Mg, 0.f);   // zeros exist outside band
                else                   m = 0.f;              // empty band: all-zero map
                float sc = (Rn > 0.f) ? expf(Mg - m) : 0.f;
                T *= sc; Tx *= sc; Ty *= sc;
                if (Rn < 2048.f) {
                    const float NTOT  = 4194304.f;      // H*W
                    const float SXROW = 2096128.f;      // W*(W-1)/2
                    const float SXTOT = 4292870144.f;   // H * SXROW
                    const float SYTOT = 4292870144.f;   // W * H*(H-1)/2
                    float e0 = expf(-m);
                    T  += (NTOT  - Rn * 2048.f) * e0;
                    Tx += (SXTOT - Rn * SXROW ) * e0;
                    Ty += (SYTOT - 2048.f * (0.5f * (float)(r0 + r1) * Rn)) * e0;
                }
                float ax = Tx / T, ay = Ty / T;
                s_ay = ay;
                out[i * 2 + 0] = ax; out[i * 2 + 1] = ay;
            }
        }
        __syncthreads();                    // BAR B
        yB = yA;
        yA = s_ay;
    }
}

extern "C" void kernel_launch(void* const* d_in, const int* in_sizes, int n_in,
                              void* d_out, int out_size) {
    const float *hm = (const float*)d_in[0];
    float *out = (float*)d_out;
    (void)in_sizes; (void)n_in; (void)out_size;

    phase0_kernel<<<NB, NT>>>(hm);
    bands_kernel<<<1, NT>>>(hm, out);
}